// round 2
// baseline (speedup 1.0000x reference)
#include <cuda_runtime.h>

// out = noised + 0.1f * noise   (elementwise, N = 50,331,648 fp32)
// HBM-streaming: 4x float4 per thread (MLP=8 front-batched LDG.128),
// evict-first cache hints on all global traffic (zero reuse workload).

#define VPT 4   // float4 vectors per thread

__global__ void __launch_bounds__(256) gaussian_noise_axpy4x4(
    const float4* __restrict__ noised,
    const float4* __restrict__ noise,
    float4* __restrict__ out,
    int n4)
{
    int base = blockIdx.x * (blockDim.x * VPT) + threadIdx.x;

    if (base + (VPT - 1) * blockDim.x < n4) {
        // Fast path: all 4 vectors in range. Front-batch all 8 loads.
        float4 a0 = __ldcs(&noised[base + 0 * blockDim.x]);
        float4 a1 = __ldcs(&noised[base + 1 * blockDim.x]);
        float4 a2 = __ldcs(&noised[base + 2 * blockDim.x]);
        float4 a3 = __ldcs(&noised[base + 3 * blockDim.x]);
        float4 b0 = __ldcs(&noise [base + 0 * blockDim.x]);
        float4 b1 = __ldcs(&noise [base + 1 * blockDim.x]);
        float4 b2 = __ldcs(&noise [base + 2 * blockDim.x]);
        float4 b3 = __ldcs(&noise [base + 3 * blockDim.x]);

        float4 r0, r1, r2, r3;
        r0.x = fmaf(0.1f, b0.x, a0.x); r0.y = fmaf(0.1f, b0.y, a0.y);
        r0.z = fmaf(0.1f, b0.z, a0.z); r0.w = fmaf(0.1f, b0.w, a0.w);
        r1.x = fmaf(0.1f, b1.x, a1.x); r1.y = fmaf(0.1f, b1.y, a1.y);
        r1.z = fmaf(0.1f, b1.z, a1.z); r1.w = fmaf(0.1f, b1.w, a1.w);
        r2.x = fmaf(0.1f, b2.x, a2.x); r2.y = fmaf(0.1f, b2.y, a2.y);
        r2.z = fmaf(0.1f, b2.z, a2.z); r2.w = fmaf(0.1f, b2.w, a2.w);
        r3.x = fmaf(0.1f, b3.x, a3.x); r3.y = fmaf(0.1f, b3.y, a3.y);
        r3.z = fmaf(0.1f, b3.z, a3.z); r3.w = fmaf(0.1f, b3.w, a3.w);

        __stcs(&out[base + 0 * blockDim.x], r0);
        __stcs(&out[base + 1 * blockDim.x], r1);
        __stcs(&out[base + 2 * blockDim.x], r2);
        __stcs(&out[base + 3 * blockDim.x], r3);
    } else {
        // Guarded path (last partial block only).
        #pragma unroll
        for (int v = 0; v < VPT; v++) {
            int i = base + v * blockDim.x;
            if (i < n4) {
                float4 a = __ldcs(&noised[i]);
                float4 b = __ldcs(&noise[i]);
                float4 r;
                r.x = fmaf(0.1f, b.x, a.x);
                r.y = fmaf(0.1f, b.y, a.y);
                r.z = fmaf(0.1f, b.z, a.z);
                r.w = fmaf(0.1f, b.w, a.w);
                __stcs(&out[i], r);
            }
        }
    }
}

// Scalar tail (n not divisible by 4; not expected for this shape).
__global__ void gaussian_noise_axpy_tail(
    const float* __restrict__ noised,
    const float* __restrict__ noise,
    float* __restrict__ out,
    int start, int n)
{
    int i = start + blockIdx.x * blockDim.x + threadIdx.x;
    if (i < n) {
        out[i] = fmaf(0.1f, noise[i], noised[i]);
    }
}

extern "C" void kernel_launch(void* const* d_in, const int* in_sizes, int n_in,
                              void* d_out, int out_size)
{
    const float* noised = (const float*)d_in[0];
    const float* noise  = (const float*)d_in[1];
    float* out = (float*)d_out;
    int n = in_sizes[0];

    int n4 = n >> 2;
    if (n4 > 0) {
        const int threads = 256;
        const int elems_per_block = threads * VPT;          // 1024 float4s
        int blocks = (n4 + elems_per_block - 1) / elems_per_block;
        gaussian_noise_axpy4x4<<<blocks, threads>>>(
            (const float4*)noised, (const float4*)noise, (float4*)out, n4);
    }
    int done = n4 << 2;
    if (done < n) {
        int rem = n - done;
        gaussian_noise_axpy_tail<<<(rem + 255) / 256, 256>>>(noised, noise, out, done, n);
    }
}